// round 3
// baseline (speedup 1.0000x reference)
#include <cuda_runtime.h>

#define NB  16
#define NC  512
#define NHW 4096
#define NIP 10

// ---------------- scratch (static device globals; no allocations) ----------------
__device__ float g_WsA[NB*NC*NC];   // split-K half 0 of Gram
__device__ float g_WsB[NB*NC*NC];   // split-K half 1 of Gram
__device__ float g_Ws [NB*NC*NC];   // summed Gram
__device__ float g_v  [NB*NC];      // v after 10 power iterations
__device__ float g_u  [NB*NHW];     // unnormalized u = X^T v
__device__ float g_upart[NB*16];    // per-block partial sum of u^2
__device__ float g_uinv [NB];       // 1/||u||

// ---------------- packed fp32x2 helpers (Blackwell dual-FP32 path) ----------------
__device__ __forceinline__ unsigned long long pk2(float lo, float hi) {
    unsigned long long r;
    asm("mov.b64 %0, {%1,%2};" : "=l"(r) : "f"(lo), "f"(hi));
    return r;
}
__device__ __forceinline__ void fma2(unsigned long long &c,
                                     unsigned long long a,
                                     unsigned long long b) {
    asm("fma.rn.f32x2 %0, %1, %2, %0;" : "+l"(c) : "l"(a), "l"(b));
}

// =====================================================================
// Kernel 1: Gram. Ws[b] = X[b] * X[b]^T, X is (512 x 4096) row-major.
// Symmetric: only upper-triangular 128x128 tile pairs (10 of 16), each
// result written to (i,j) and (j,i). Split-K=2 into g_WsA / g_WsB.
// BM=BN=128, BK=16, 256 threads, 8x8 microtile via fma.rn.f32x2.
// =====================================================================
__global__ __launch_bounds__(256, 2)
void gram_kernel(const float* __restrict__ x) {
    const int b = blockIdx.y;
    const int z = blockIdx.z;           // split-K half
    // map blockIdx.x in [0,10) -> upper-tri pair (ti<=tj) over 4x4 tile grid
    int ti = 0, r = blockIdx.x;
    while (r >= 4 - ti) { r -= 4 - ti; ti++; }
    const int tj = ti + r;
    const int i0 = ti * 128, j0 = tj * 128;

    const float* __restrict__ Xb = x + (size_t)b * NC * NHW;
    float* __restrict__ Wb = (z ? g_WsB : g_WsA) + (size_t)b * NC * NC;

    __shared__ float As[16][132];   // [k][m], pad 132 for store-conflict relief
    __shared__ float Bs[16][132];   // [k][n]

    const int tid = threadIdx.x;
    const int tx  = tid & 15;       // n-group
    const int ty  = tid >> 4;       // m-group
    const int lrow = tid >> 2;      // loader: rows lrow, lrow+64
    const int lc4  = tid & 3;       // loader: float4 column within BK=16

    unsigned long long acc[4][8];   // 4 m-pairs x 8 n (packed fp32x2)
    #pragma unroll
    for (int i = 0; i < 4; i++)
        #pragma unroll
        for (int j = 0; j < 8; j++) acc[i][j] = 0ULL;

    const int kbase0 = z * 2048;

    // prefetch tile 0
    float4 pa0, pa1, pb0, pb1;
    {
        const float* pA = Xb + (size_t)(i0 + lrow) * NHW + kbase0 + 4 * lc4;
        pa0 = *(const float4*)pA;
        pa1 = *(const float4*)(pA + 64 * NHW);
        const float* pB = Xb + (size_t)(j0 + lrow) * NHW + kbase0 + 4 * lc4;
        pb0 = *(const float4*)pB;
        pb1 = *(const float4*)(pB + 64 * NHW);
    }

    for (int kt = 0; kt < 128; kt++) {
        __syncthreads();
        {
            const int kk = 4 * lc4;
            As[kk+0][lrow]    = pa0.x; As[kk+1][lrow]    = pa0.y;
            As[kk+2][lrow]    = pa0.z; As[kk+3][lrow]    = pa0.w;
            As[kk+0][lrow+64] = pa1.x; As[kk+1][lrow+64] = pa1.y;
            As[kk+2][lrow+64] = pa1.z; As[kk+3][lrow+64] = pa1.w;
            Bs[kk+0][lrow]    = pb0.x; Bs[kk+1][lrow]    = pb0.y;
            Bs[kk+2][lrow]    = pb0.z; Bs[kk+3][lrow]    = pb0.w;
            Bs[kk+0][lrow+64] = pb1.x; Bs[kk+1][lrow+64] = pb1.y;
            Bs[kk+2][lrow+64] = pb1.z; Bs[kk+3][lrow+64] = pb1.w;
        }
        __syncthreads();

        if (kt < 127) {
            const int kb = kbase0 + (kt + 1) * 16;
            const float* pA = Xb + (size_t)(i0 + lrow) * NHW + kb + 4 * lc4;
            pa0 = *(const float4*)pA;
            pa1 = *(const float4*)(pA + 64 * NHW);
            const float* pB = Xb + (size_t)(j0 + lrow) * NHW + kb + 4 * lc4;
            pb0 = *(const float4*)pB;
            pb1 = *(const float4*)(pB + 64 * NHW);
        }

        #pragma unroll
        for (int k = 0; k < 16; k++) {
            const float4 a0 = *(const float4*)&As[k][4 * ty];
            const float4 a1 = *(const float4*)&As[k][64 + 4 * ty];
            const float4 b0 = *(const float4*)&Bs[k][4 * tx];
            const float4 b1 = *(const float4*)&Bs[k][64 + 4 * tx];
            unsigned long long a2[4];
            a2[0] = pk2(a0.x, a0.y); a2[1] = pk2(a0.z, a0.w);
            a2[2] = pk2(a1.x, a1.y); a2[3] = pk2(a1.z, a1.w);
            const float bv[8] = {b0.x, b0.y, b0.z, b0.w, b1.x, b1.y, b1.z, b1.w};
            #pragma unroll
            for (int n = 0; n < 8; n++) {
                const unsigned long long b2 = pk2(bv[n], bv[n]);
                fma2(acc[0][n], a2[0], b2);
                fma2(acc[1][n], a2[1], b2);
                fma2(acc[2][n], a2[2], b2);
                fma2(acc[3][n], a2[3], b2);
            }
        }
    }

    // unpack accumulators: cf[lm][ln], lm/ln in 0..7 (chunked 4+4)
    float cf[8][8];
    #pragma unroll
    for (int mp = 0; mp < 4; mp++)
        #pragma unroll
        for (int n = 0; n < 8; n++) {
            union { unsigned long long u; float2 f; } cvt;
            cvt.u = acc[mp][n];
            cf[2 * mp + 0][n] = cvt.f.x;
            cf[2 * mp + 1][n] = cvt.f.y;
        }
    // note: lm index above is (pair-major): lm = 2*mp+{0,1} maps to
    // m-offset: mp in {0,1} -> chunk0 rows 4ty + (2*mp+lohi); mp in {2,3} -> chunk1
    // i.e. lm 0..3 -> 4ty+lm (chunk0), lm 4..7 -> 64+4ty+(lm-4) (chunk1). This holds
    // because a2[0..1] covered m = 4ty..4ty+3 and a2[2..3] covered 64+4ty..64+4ty+3.

    // direct writes: rows m, cols n-chunks (float4, coalesced across tx)
    #pragma unroll
    for (int lm = 0; lm < 8; lm++) {
        const int mrow = i0 + ((lm < 4) ? (4 * ty + lm) : (64 + 4 * ty + (lm - 4)));
        float4 w0 = make_float4(cf[lm][0], cf[lm][1], cf[lm][2], cf[lm][3]);
        float4 w1 = make_float4(cf[lm][4], cf[lm][5], cf[lm][6], cf[lm][7]);
        *(float4*)&Wb[(size_t)mrow * NC + j0 + 4 * tx]      = w0;
        *(float4*)&Wb[(size_t)mrow * NC + j0 + 64 + 4 * tx] = w1;
    }
    // transposed writes (symmetry): rows n, cols m-chunks
    #pragma unroll
    for (int ln = 0; ln < 8; ln++) {
        const int nrow = j0 + ((ln < 4) ? (4 * tx + ln) : (64 + 4 * tx + (ln - 4)));
        float4 w0 = make_float4(cf[0][ln], cf[1][ln], cf[2][ln], cf[3][ln]);
        float4 w1 = make_float4(cf[4][ln], cf[5][ln], cf[6][ln], cf[7][ln]);
        *(float4*)&Wb[(size_t)nrow * NC + i0 + 4 * ty]      = w0;
        *(float4*)&Wb[(size_t)nrow * NC + i0 + 64 + 4 * ty] = w1;
    }
}

// =====================================================================
// Kernel 2: sum the two split-K halves.
// =====================================================================
__global__ void addws_kernel() {
    const size_t i = (size_t)blockIdx.x * blockDim.x + threadIdx.x;  // float4 idx
    const size_t total = (size_t)NB * NC * NC / 4;
    if (i >= total) return;
    const float4 a = ((const float4*)g_WsA)[i];
    const float4 b = ((const float4*)g_WsB)[i];
    ((float4*)g_Ws)[i] = make_float4(a.x + b.x, a.y + b.y, a.z + b.z, a.w + b.w);
}

// =====================================================================
// Kernel 3: 10 power iterations. One block per batch, 512 threads.
// Uses Ws symmetry: y[c] = sum_d Ws[d][c] * v[d]  (coalesced over c).
// =====================================================================
__global__ __launch_bounds__(512)
void power_kernel(const float* __restrict__ vin) {
    const int b = blockIdx.x;
    const int c = threadIdx.x;
    __shared__ float vs[NC];
    __shared__ float red[16];
    __shared__ float tot;

    const float* __restrict__ Wb = g_Ws + (size_t)b * NC * NC;
    vs[c] = vin[b * NC + c];
    __syncthreads();

    for (int it = 0; it < NIP; it++) {
        float acc = 0.f;
        #pragma unroll 16
        for (int d = 0; d < NC; d++)
            acc += Wb[(size_t)d * NC + c] * vs[d];

        float s = acc * acc;
        #pragma unroll
        for (int o = 16; o > 0; o >>= 1)
            s += __shfl_xor_sync(0xffffffffu, s, o);
        if ((c & 31) == 0) red[c >> 5] = s;
        __syncthreads();                 // also guarantees all vs reads are done
        if (c == 0) {
            float t = 0.f;
            #pragma unroll
            for (int i = 0; i < 16; i++) t += red[i];
            tot = t;
        }
        __syncthreads();
        vs[c] = acc * rsqrtf(tot);
        __syncthreads();
    }
    g_v[b * NC + c] = vs[c];
}

// =====================================================================
// Kernel 4: u = X^T v (unnormalized) + per-block partial ||u||^2.
// grid (16 n-blocks, 16 batches), 256 threads, each thread one n.
// =====================================================================
__global__ __launch_bounds__(256)
void u_kernel(const float* __restrict__ x) {
    const int b = blockIdx.y;
    const int n = blockIdx.x * 256 + threadIdx.x;
    __shared__ float vs[NC];
    __shared__ float red[8];
    vs[threadIdx.x]       = g_v[b * NC + threadIdx.x];
    vs[threadIdx.x + 256] = g_v[b * NC + threadIdx.x + 256];
    __syncthreads();

    const float* __restrict__ Xb = x + (size_t)b * NC * NHW;
    float acc = 0.f;
    #pragma unroll 8
    for (int c = 0; c < NC; c++)
        acc += Xb[(size_t)c * NHW + n] * vs[c];
    g_u[b * NHW + n] = acc;

    float s = acc * acc;
    #pragma unroll
    for (int o = 16; o > 0; o >>= 1)
        s += __shfl_xor_sync(0xffffffffu, s, o);
    if ((threadIdx.x & 31) == 0) red[threadIdx.x >> 5] = s;
    __syncthreads();
    if (threadIdx.x == 0) {
        float t = 0.f;
        #pragma unroll
        for (int i = 0; i < 8; i++) t += red[i];
        g_upart[b * 16 + blockIdx.x] = t;
    }
}

// =====================================================================
// Kernel 5: reduce partials -> 1/||u|| per batch. 1 block, 512 threads.
// =====================================================================
__global__ void unorm_kernel() {
    const int w = threadIdx.x >> 5;    // warp = batch
    const int l = threadIdx.x & 31;
    float v = (l < 16) ? g_upart[w * 16 + l] : 0.f;
    #pragma unroll
    for (int o = 8; o > 0; o >>= 1)
        v += __shfl_xor_sync(0xffffffffu, v, o);
    if (l == 0) g_uinv[w] = rsqrtf(v);
}

// =====================================================================
// Kernel 6: out = x + (v * 1/||u||) outer u. float4 streaming.
// =====================================================================
__global__ __launch_bounds__(256)
void final_kernel(const float* __restrict__ x, float* __restrict__ out) {
    const size_t i = (size_t)blockIdx.x * blockDim.x + threadIdx.x;  // float4 idx
    const size_t total = (size_t)NB * NC * NHW / 4;
    if (i >= total) return;
    const size_t e = i * 4;
    const int b = (int)(e >> 21);            // NC*NHW = 2^21
    const int rem = (int)(e & ((1u << 21) - 1));
    const int c = rem >> 12;                 // NHW = 2^12
    const int n = rem & (NHW - 1);
    const float vc = g_v[b * NC + c] * g_uinv[b];
    const float4 u4 = *(const float4*)&g_u[b * NHW + n];
    const float4 xv = *(const float4*)&x[e];
    float4 o;
    o.x = xv.x + vc * u4.x;
    o.y = xv.y + vc * u4.y;
    o.z = xv.z + vc * u4.z;
    o.w = xv.w + vc * u4.w;
    *(float4*)&out[e] = o;
}

// =====================================================================
extern "C" void kernel_launch(void* const* d_in, const int* in_sizes, int n_in,
                              void* d_out, int out_size) {
    const float* x  = (const float*)d_in[0];
    const float* v0 = (const float*)d_in[1];
    float* out = (float*)d_out;

    gram_kernel<<<dim3(10, NB, 2), 256>>>(x);
    {
        const int total4 = NB * NC * NC / 4;
        addws_kernel<<<(total4 + 255) / 256, 256>>>();
    }
    power_kernel<<<NB, 512>>>(v0);
    u_kernel<<<dim3(16, NB), 256>>>(x);
    unorm_kernel<<<1, 512>>>();
    {
        const int total4 = NB * NC * NHW / 4;
        final_kernel<<<(total4 + 255) / 256, 256>>>(x, out);
    }
}

// round 5
// speedup vs baseline: 1.2555x; 1.2555x over previous
#include <cuda_runtime.h>
#include <cuda_bf16.h>
#include <cstdint>

#define NB  16
#define NC  512
#define NHW 4096
#define NIP 10

// ---------------- scratch (static device globals; no allocations) ----------------
__device__ __align__(16) __nv_bfloat16 g_xh[NB*NC*NHW];   // bf16 copy of x (64MB)
__device__ float g_Ws [NB*NC*NC];    // Gram (16MB)
__device__ float g_v  [NB*NC];       // v after 10 power iterations
__device__ float g_u  [NB*NHW];      // unnormalized u = X^T v
__device__ float g_upar[NB*8*NHW];   // c-chunk partials of u (2MB)
__device__ float g_uinv [NB];        // 1/||u||

// ================= PTX helpers =================
__device__ __forceinline__ uint32_t smem_u32(const void* p) {
    uint32_t a;
    asm("{ .reg .u64 t; cvta.to.shared.u64 t, %1; cvt.u32.u64 %0, t; }" : "=r"(a) : "l"(p));
    return a;
}
__device__ __forceinline__ void cp16(uint32_t dst, const void* gsrc) {
    asm volatile("cp.async.cg.shared.global [%0], [%1], 16;"
                 :: "r"(dst), "l"(__cvta_generic_to_global(gsrc)) : "memory");
}
#define CP_COMMIT() asm volatile("cp.async.commit_group;" ::: "memory")

__device__ __forceinline__ void ldsm4(uint32_t* r, uint32_t addr) {
    asm volatile("ldmatrix.sync.aligned.m8n8.x4.shared.b16 {%0,%1,%2,%3}, [%4];"
        : "=r"(r[0]), "=r"(r[1]), "=r"(r[2]), "=r"(r[3]) : "r"(addr));
}
__device__ __forceinline__ void mma16816(float* d, const uint32_t* a, uint32_t b0, uint32_t b1) {
    asm volatile("mma.sync.aligned.m16n8k16.row.col.f32.bf16.bf16.f32 "
        "{%0,%1,%2,%3}, {%4,%5,%6,%7}, {%8,%9}, {%0,%1,%2,%3};"
        : "+f"(d[0]), "+f"(d[1]), "+f"(d[2]), "+f"(d[3])
        : "r"(a[0]), "r"(a[1]), "r"(a[2]), "r"(a[3]), "r"(b0), "r"(b1));
}

// =====================================================================
// Kernel 0: convert x (f32) -> g_xh (bf16). 32M elems, float4 granularity.
// =====================================================================
__global__ __launch_bounds__(256)
void conv_kernel(const float* __restrict__ x) {
    const size_t i = (size_t)blockIdx.x * 256 + threadIdx.x;   // float4 index
    const float4 v = ((const float4*)x)[i];
    __nv_bfloat162 lo = __floats2bfloat162_rn(v.x, v.y);
    __nv_bfloat162 hi = __floats2bfloat162_rn(v.z, v.w);
    union { struct { __nv_bfloat162 a, b; } h; uint2 u; } cv;
    cv.h.a = lo; cv.h.b = hi;
    ((uint2*)g_xh)[i] = cv.u;
}

// =====================================================================
// Kernel 1: Gram via bf16 mma.sync (HMMA, tensor pipe).
// grid (10 tile-pairs, 16 batches). 256 threads = 8 warps (2m x 4n),
// warp tile 64x32 (4x4 of m16n8k16). BK=32, 3-stage cp.async pipeline.
// Smem rows padded to 80B (40 bf16) — conflict-free ldmatrix + cp stores.
// Epilogue: full 128x128 C staged in smem (stride 129), symmetric writes.
// =====================================================================
#define BK 32
#define ASTR 40                       // bf16 elems per smem row (80 bytes)
#define TILE_BYTES (128 * ASTR * 2)   // 10240 per operand tile
#define STAGE_BYTES (2 * TILE_BYTES)  // A + B = 20480
#define GRAM_SMEM (128 * 129 * 4)     // 66048 >= 3*STAGE_BYTES (61440)

__global__ __launch_bounds__(256, 2)
void gram_mma(void) {
    extern __shared__ char ds[];
    const uint32_t sb = smem_u32(ds);
    const int tid = threadIdx.x;
    const int wid = tid >> 5, lane = tid & 31;

    const int b = blockIdx.y;
    int ti = 0, r = blockIdx.x;
    while (r >= 4 - ti) { r -= 4 - ti; ti++; }
    const int tj = ti + r;
    const int i0 = ti * 128, j0 = tj * 128;
    const bool diag = (ti == tj);

    const __nv_bfloat16* __restrict__ Xb = g_xh + (size_t)b * NC * NHW;
    float* __restrict__ Wb = g_Ws + (size_t)b * NC * NC;

    // loader indices: 2 x 16B per thread per operand tile
    const int lrow0 = tid >> 2;          // id = tid       -> row tid>>2
    const int lrow1 = (256 + tid) >> 2;  // id = 256 + tid
    const int lkq   = tid & 3;

    auto load_chunk = [&](int c) {
        const uint32_t ab = sb + (uint32_t)(c % 3) * STAGE_BYTES;
        const __nv_bfloat16* gA = Xb + (size_t)i0 * NHW + c * BK;
        cp16(ab + lrow0 * 80 + lkq * 16, gA + (size_t)lrow0 * NHW + lkq * 8);
        cp16(ab + lrow1 * 80 + lkq * 16, gA + (size_t)lrow1 * NHW + lkq * 8);
        if (!diag) {
            const uint32_t bb = ab + TILE_BYTES;
            const __nv_bfloat16* gB = Xb + (size_t)j0 * NHW + c * BK;
            cp16(bb + lrow0 * 80 + lkq * 16, gB + (size_t)lrow0 * NHW + lkq * 8);
            cp16(bb + lrow1 * 80 + lkq * 16, gB + (size_t)lrow1 * NHW + lkq * 8);
        }
        CP_COMMIT();
    };

    load_chunk(0); load_chunk(1); load_chunk(2);

    // per-lane ldmatrix address offsets (bytes)
    const uint32_t aoff = (uint32_t)((lane & 15) * 80 + (lane >> 4) * 16);
    const uint32_t boff = (uint32_t)(((lane & 7) | (((lane >> 4) & 1) << 3)) * 80
                                     + ((lane >> 3) & 1) * 16);
    const uint32_t wm = (uint32_t)((wid & 1) * 64) * 80;   // warp m0 * stride
    const uint32_t wn = (uint32_t)((wid >> 1) * 32) * 80;  // warp n0 * stride

    float acc[4][4][4];
    #pragma unroll
    for (int mt = 0; mt < 4; mt++)
        #pragma unroll
        for (int nt = 0; nt < 4; nt++)
            #pragma unroll
            for (int q = 0; q < 4; q++) acc[mt][nt][q] = 0.f;

    for (int c = 0; c < 128; c++) {
        if (c < 126)      asm volatile("cp.async.wait_group 2;" ::: "memory");
        else if (c == 126) asm volatile("cp.async.wait_group 1;" ::: "memory");
        else               asm volatile("cp.async.wait_group 0;" ::: "memory");
        __syncthreads();

        const uint32_t ab = sb + (uint32_t)(c % 3) * STAGE_BYTES;
        const uint32_t bb = diag ? ab : (ab + TILE_BYTES);

        #pragma unroll
        for (int ks = 0; ks < 2; ks++) {
            uint32_t af[4][4], bf[2][4];
            #pragma unroll
            for (int mt = 0; mt < 4; mt++)
                ldsm4(af[mt], ab + wm + (uint32_t)(mt * 1280 + ks * 32) + aoff);
            #pragma unroll
            for (int nh = 0; nh < 2; nh++)
                ldsm4(bf[nh], bb + wn + (uint32_t)(nh * 1280 + ks * 32) + boff);
            #pragma unroll
            for (int mt = 0; mt < 4; mt++)
                #pragma unroll
                for (int nt = 0; nt < 4; nt++)
                    mma16816(acc[mt][nt], af[mt], bf[nt >> 1][2 * (nt & 1)],
                             bf[nt >> 1][2 * (nt & 1) + 1]);
        }
        __syncthreads();   // all reads of stage c%3 done before overwrite
        if (c + 3 < 128) load_chunk(c + 3);
    }
    __syncthreads();

    // ---- epilogue: stage full 128x128 C in smem (stride 129 floats) ----
    float* st = (float*)ds;
    {
        const int gid = lane >> 2, tig = lane & 3;
        const int wm0 = (wid & 1) * 64, wn0 = (wid >> 1) * 32;
        #pragma unroll
        for (int mt = 0; mt < 4; mt++)
            #pragma unroll
            for (int nt = 0; nt < 4; nt++) {
                const int m = wm0 + mt * 16 + gid;
                const int n = wn0 + nt * 8 + tig * 2;
                st[m * 129 + n]           = acc[mt][nt][0];
                st[m * 129 + n + 1]       = acc[mt][nt][1];
                st[(m + 8) * 129 + n]     = acc[mt][nt][2];
                st[(m + 8) * 129 + n + 1] = acc[mt][nt][3];
            }
    }
    __syncthreads();

    // direct block (i0, j0)
    #pragma unroll
    for (int it = 0; it < 16; it++) {
        const int e = it * 256 + tid;
        const int row = e >> 5, c4 = e & 31;
        float4 w = make_float4(st[row * 129 + c4 * 4],     st[row * 129 + c4 * 4 + 1],
                               st[row * 129 + c4 * 4 + 2], st[row * 129 + c4 * 4 + 3]);
        *(float4*)&Wb[(size_t)(i0 + row) * NC + j0 + c4 * 4] = w;
    }
    // transposed block (j0, i0)
    if (!diag) {
        #pragma unroll
        for (int it = 0; it < 16; it++) {
            const int e = it * 256 + tid;
            const int n = e >> 5, m4 = e & 31;
            float4 w = make_float4(st[(m4 * 4)     * 129 + n], st[(m4 * 4 + 1) * 129 + n],
                                   st[(m4 * 4 + 2) * 129 + n], st[(m4 * 4 + 3) * 129 + n]);
            *(float4*)&Wb[(size_t)(j0 + n) * NC + i0 + m4 * 4] = w;
        }
    }
}

// =====================================================================
// Kernel 2: 10 power iterations. One block/batch, 1024 threads (2-way d-split).
// y[c] = sum_d Ws[d][c] * v[d]  (coalesced over c; Ws symmetric).
// =====================================================================
__global__ __launch_bounds__(1024)
void power_kernel(const float* __restrict__ vin) {
    const int b = blockIdx.x, t = threadIdx.x;
    const int c = t & 511, h = t >> 9;
    __shared__ float vs[NC];
    __shared__ float part[1024];
    __shared__ float red[16];
    __shared__ float tot;

    const float* __restrict__ Wb = g_Ws + (size_t)b * NC * NC;
    if (t < NC) vs[t] = vin[b * NC + t];
    __syncthreads();

    for (int it = 0; it < NIP; it++) {
        const float* __restrict__ Wp = Wb + (size_t)(h * 256) * NC + c;
        float acc = 0.f;
        #pragma unroll 16
        for (int d = 0; d < 256; d++)
            acc += Wp[(size_t)d * NC] * vs[h * 256 + d];
        part[t] = acc;
        __syncthreads();

        float nv = 0.f;
        if (t < NC) {
            nv = part[t] + part[t + 512];
            float s = nv * nv;
            #pragma unroll
            for (int o = 16; o > 0; o >>= 1)
                s += __shfl_xor_sync(0xffffffffu, s, o);
            if ((t & 31) == 0) red[t >> 5] = s;
        }
        __syncthreads();
        if (t == 0) {
            float x = 0.f;
            #pragma unroll
            for (int i = 0; i < 16; i++) x += red[i];
            tot = x;
        }
        __syncthreads();
        if (t < NC) vs[t] = nv * rsqrtf(tot);
        __syncthreads();
    }
    if (t < NC) g_v[b * NC + t] = vs[t];
}

// =====================================================================
// Kernel 3: u partials. grid (4 n-blocks, 8 c-chunks, 16 batches), 256 thr.
// =====================================================================
__global__ __launch_bounds__(256)
void u_part_kernel(const float* __restrict__ x) {
    const int b = blockIdx.z, ch = blockIdx.y;
    const int n0 = blockIdx.x * 1024 + threadIdx.x * 4;
    __shared__ float vsh[64];
    if (threadIdx.x < 64) vsh[threadIdx.x] = g_v[b * NC + ch * 64 + threadIdx.x];
    __syncthreads();

    const float* __restrict__ Xp = x + (size_t)b * NC * NHW + (size_t)(ch * 64) * NHW;
    float4 acc = make_float4(0.f, 0.f, 0.f, 0.f);
    #pragma unroll 8
    for (int cc = 0; cc < 64; cc++) {
        const float4 xv = *(const float4*)&Xp[(size_t)cc * NHW + n0];
        const float vv = vsh[cc];
        acc.x += vv * xv.x; acc.y += vv * xv.y;
        acc.z += vv * xv.z; acc.w += vv * xv.w;
    }
    *(float4*)&g_upar[(size_t)(b * 8 + ch) * NHW + n0] = acc;
}

// =====================================================================
// Kernel 4: reduce c-chunk partials -> g_u, compute 1/||u||. grid 16, 512 thr.
// =====================================================================
__global__ __launch_bounds__(512)
void u_reduce_kernel() {
    const int b = blockIdx.x, t = threadIdx.x;
    __shared__ float red[16];
    float sq = 0.f;
    #pragma unroll
    for (int j = 0; j < 8; j++) {
        const int n = j * 512 + t;
        float s = 0.f;
        #pragma unroll
        for (int ch = 0; ch < 8; ch++)
            s += g_upar[(size_t)(b * 8 + ch) * NHW + n];
        g_u[b * NHW + n] = s;
        sq += s * s;
    }
    #pragma unroll
    for (int o = 16; o > 0; o >>= 1)
        sq += __shfl_xor_sync(0xffffffffu, sq, o);
    if ((t & 31) == 0) red[t >> 5] = sq;
    __syncthreads();
    if (t == 0) {
        float x = 0.f;
        #pragma unroll
        for (int i = 0; i < 16; i++) x += red[i];
        g_uinv[b] = rsqrtf(x);
    }
}

// =====================================================================
// Kernel 5: out = x + (v * 1/||u||) outer u. float4 streaming.
// =====================================================================
__global__ __launch_bounds__(256)
void final_kernel(const float* __restrict__ x, float* __restrict__ out) {
    const size_t i = (size_t)blockIdx.x * 256 + threadIdx.x;   // float4 idx
    const size_t e = i * 4;
    const int b   = (int)(e >> 21);                 // NC*NHW = 2^21
    const int rem = (int)(e & ((1u << 21) - 1));
    const int c   = rem >> 12;                      // NHW = 2^12
    const int n   = rem & (NHW - 1);
    const float vc = g_v[b * NC + c] * g_uinv[b];
    const float4 u4 = *(const float4*)&g_u[b * NHW + n];
    const float4 xv = *(const float4*)&x[e];
    float4 o;
    o.x = xv.x + vc * u4.x;
    o.y = xv.y + vc * u4.y;
    o.z = xv.z + vc * u4.z;
    o.w = xv.w + vc * u4.w;
    *(float4*)&out[e] = o;
}

// =====================================================================
extern "C" void kernel_launch(void* const* d_in, const int* in_sizes, int n_in,
                              void* d_out, int out_size) {
    const float* x  = (const float*)d_in[0];
    const float* v0 = (const float*)d_in[1];
    float* out = (float*)d_out;

    cudaFuncSetAttribute(gram_mma, cudaFuncAttributeMaxDynamicSharedMemorySize, GRAM_SMEM);

    conv_kernel<<<32768, 256>>>(x);                    // 32M elems / (256*4)
    gram_mma<<<dim3(10, NB), 256, GRAM_SMEM>>>();
    power_kernel<<<NB, 1024>>>(v0);
    u_part_kernel<<<dim3(4, 8, NB), 256>>>(x);
    u_reduce_kernel<<<NB, 512>>>();
    final_kernel<<<32768, 256>>>(x, out);
}

// round 6
// speedup vs baseline: 2.4648x; 1.9631x over previous
#include <cuda_runtime.h>
#include <cuda_bf16.h>
#include <cstdint>

#define NB  16
#define NC  512
#define NHW 4096
#define NIP 10

// ---------------- scratch (static device globals; no allocations) ----------------
__device__ __align__(16) __nv_bfloat16 g_xh[NB*NC*NHW];    // bf16 copy of x (64MB)
__device__ float g_Ws [NB*NC*NC];                          // Gram fp32 (16MB)
__device__ __align__(16) __nv_bfloat16 g_Wsh[NB*NC*NC];    // Gram bf16 (8MB)
__device__ float g_v  [NB*NC];       // v after 10 power iterations
__device__ float g_u  [NB*NHW];      // unnormalized u = X^T v
__device__ float g_upar[NB*8*NHW];   // c-chunk partials of u (2MB)
__device__ float g_uinv [NB];        // 1/||u||

// ================= PTX helpers =================
__device__ __forceinline__ uint32_t smem_u32(const void* p) {
    uint32_t a;
    asm("{ .reg .u64 t; cvta.to.shared.u64 t, %1; cvt.u32.u64 %0, t; }" : "=r"(a) : "l"(p));
    return a;
}
__device__ __forceinline__ void cp16(uint32_t dst, const void* gsrc) {
    asm volatile("cp.async.cg.shared.global [%0], [%1], 16;"
                 :: "r"(dst), "l"(__cvta_generic_to_global(gsrc)) : "memory");
}
#define CP_COMMIT() asm volatile("cp.async.commit_group;" ::: "memory")

__device__ __forceinline__ void ldsm4(uint32_t* r, uint32_t addr) {
    asm volatile("ldmatrix.sync.aligned.m8n8.x4.shared.b16 {%0,%1,%2,%3}, [%4];"
        : "=r"(r[0]), "=r"(r[1]), "=r"(r[2]), "=r"(r[3]) : "r"(addr));
}
__device__ __forceinline__ void mma16816(float* d, const uint32_t* a, uint32_t b0, uint32_t b1) {
    asm volatile("mma.sync.aligned.m16n8k16.row.col.f32.bf16.bf16.f32 "
        "{%0,%1,%2,%3}, {%4,%5,%6,%7}, {%8,%9}, {%0,%1,%2,%3};"
        : "+f"(d[0]), "+f"(d[1]), "+f"(d[2]), "+f"(d[3])
        : "r"(a[0]), "r"(a[1]), "r"(a[2]), "r"(a[3]), "r"(b0), "r"(b1));
}
__device__ __forceinline__ float bflo(uint32_t p) { return __uint_as_float(p << 16); }
__device__ __forceinline__ float bfhi(uint32_t p) { return __uint_as_float(p & 0xffff0000u); }

// =====================================================================
// Kernel 0: convert x (f32) -> g_xh (bf16). 32M elems, float4 granularity.
// =====================================================================
__global__ __launch_bounds__(256)
void conv_kernel(const float* __restrict__ x) {
    const size_t i = (size_t)blockIdx.x * 256 + threadIdx.x;   // float4 index
    const float4 v = ((const float4*)x)[i];
    __nv_bfloat162 lo = __floats2bfloat162_rn(v.x, v.y);
    __nv_bfloat162 hi = __floats2bfloat162_rn(v.z, v.w);
    union { struct { __nv_bfloat162 a, b; } h; uint2 u; } cv;
    cv.h.a = lo; cv.h.b = hi;
    ((uint2*)g_xh)[i] = cv.u;
}

// =====================================================================
// Kernel 1: Gram via bf16 mma.sync (HMMA). 512 threads = 16 warps (4m x 4n),
// warp tile 32x32 (2x4 of m16n8k16) -> 32 acc regs/thread (no spill).
// BK=32, 3-stage cp.async pipeline; smem rows padded to 80B.
// Epilogue: stage 128x128 C in smem, write fp32 Ws + bf16 Ws, both blocks.
// =====================================================================
#define BK 32
#define ASTR 40                       // bf16 elems per smem row (80 bytes)
#define TILE_BYTES (128 * ASTR * 2)   // 10240 per operand tile
#define STAGE_BYTES (2 * TILE_BYTES)  // A + B = 20480
#define GRAM_SMEM (128 * 129 * 4)     // 66048 >= 3*STAGE_BYTES (61440)

__global__ __launch_bounds__(512, 1)
void gram_mma(void) {
    extern __shared__ char ds[];
    const uint32_t sb = smem_u32(ds);
    const int tid = threadIdx.x;
    const int wid = tid >> 5, lane = tid & 31;

    const int b = blockIdx.y;
    int ti = 0, r = blockIdx.x;
    while (r >= 4 - ti) { r -= 4 - ti; ti++; }
    const int tj = ti + r;
    const int i0 = ti * 128, j0 = tj * 128;
    const bool diag = (ti == tj);

    const __nv_bfloat16* __restrict__ Xb = g_xh + (size_t)b * NC * NHW;
    float* __restrict__ Wb = g_Ws + (size_t)b * NC * NC;
    __nv_bfloat16* __restrict__ Wh = g_Wsh + (size_t)b * NC * NC;

    // loader: one 16B cp.async per thread per operand tile (512 x 16B = 8KB)
    const int lrow = tid >> 2;
    const int lkq  = tid & 3;

    auto load_chunk = [&](int c) {
        const uint32_t ab = sb + (uint32_t)(c % 3) * STAGE_BYTES;
        const __nv_bfloat16* gA = Xb + (size_t)i0 * NHW + c * BK;
        cp16(ab + lrow * 80 + lkq * 16, gA + (size_t)lrow * NHW + lkq * 8);
        if (!diag) {
            const uint32_t bb = ab + TILE_BYTES;
            const __nv_bfloat16* gB = Xb + (size_t)j0 * NHW + c * BK;
            cp16(bb + lrow * 80 + lkq * 16, gB + (size_t)lrow * NHW + lkq * 8);
        }
        CP_COMMIT();
    };

    load_chunk(0); load_chunk(1); load_chunk(2);

    // per-lane ldmatrix address offsets (bytes) — verified in R5
    const uint32_t aoff = (uint32_t)((lane & 15) * 80 + (lane >> 4) * 16);
    const uint32_t boff = (uint32_t)(((lane & 7) | (((lane >> 4) & 1) << 3)) * 80
                                     + ((lane >> 3) & 1) * 16);
    const uint32_t wmB = (uint32_t)((wid & 3) * 32) * 80;   // warp m0 byte offset
    const uint32_t wnB = (uint32_t)((wid >> 2) * 32) * 80;  // warp n0 byte offset

    float acc[2][4][4];
    #pragma unroll
    for (int mt = 0; mt < 2; mt++)
        #pragma unroll
        for (int nt = 0; nt < 4; nt++)
            #pragma unroll
            for (int q = 0; q < 4; q++) acc[mt][nt][q] = 0.f;

    for (int c = 0; c < 128; c++) {
        if (c < 126)       asm volatile("cp.async.wait_group 2;" ::: "memory");
        else if (c == 126) asm volatile("cp.async.wait_group 1;" ::: "memory");
        else               asm volatile("cp.async.wait_group 0;" ::: "memory");
        __syncthreads();

        const uint32_t ab = sb + (uint32_t)(c % 3) * STAGE_BYTES;
        const uint32_t bb = diag ? ab : (ab + TILE_BYTES);

        #pragma unroll
        for (int ks = 0; ks < 2; ks++) {
            uint32_t af[2][4], bf[2][4];
            #pragma unroll
            for (int mt = 0; mt < 2; mt++)
                ldsm4(af[mt], ab + wmB + (uint32_t)(mt * 1280 + ks * 32) + aoff);
            #pragma unroll
            for (int nh = 0; nh < 2; nh++)
                ldsm4(bf[nh], bb + wnB + (uint32_t)(nh * 1280 + ks * 32) + boff);
            #pragma unroll
            for (int mt = 0; mt < 2; mt++)
                #pragma unroll
                for (int nt = 0; nt < 4; nt++)
                    mma16816(acc[mt][nt], af[mt], bf[nt >> 1][2 * (nt & 1)],
                             bf[nt >> 1][2 * (nt & 1) + 1]);
        }
        __syncthreads();   // all ldsm reads of stage c%3 done before overwrite
        if (c + 3 < 128) load_chunk(c + 3);
    }
    __syncthreads();

    // ---- epilogue: stage full 128x128 C in smem (stride 129 floats) ----
    float* st = (float*)ds;
    {
        const int gid = lane >> 2, tig = lane & 3;
        const int wm0 = (wid & 3) * 32, wn0 = (wid >> 2) * 32;
        #pragma unroll
        for (int mt = 0; mt < 2; mt++)
            #pragma unroll
            for (int nt = 0; nt < 4; nt++) {
                const int m = wm0 + mt * 16 + gid;
                const int n = wn0 + nt * 8 + tig * 2;
                st[m * 129 + n]           = acc[mt][nt][0];
                st[m * 129 + n + 1]       = acc[mt][nt][1];
                st[(m + 8) * 129 + n]     = acc[mt][nt][2];
                st[(m + 8) * 129 + n + 1] = acc[mt][nt][3];
            }
    }
    __syncthreads();

    // direct block (i0, j0): fp32 + bf16
    #pragma unroll
    for (int it = 0; it < 8; it++) {
        const int e = it * 512 + tid;
        const int row = e >> 5, c4 = e & 31;
        const float f0 = st[row * 129 + c4 * 4],     f1 = st[row * 129 + c4 * 4 + 1];
        const float f2 = st[row * 129 + c4 * 4 + 2], f3 = st[row * 129 + c4 * 4 + 3];
        *(float4*)&Wb[(size_t)(i0 + row) * NC + j0 + c4 * 4] = make_float4(f0, f1, f2, f3);
        union { struct { __nv_bfloat162 a, b; } h; uint2 u; } cv;
        cv.h.a = __floats2bfloat162_rn(f0, f1);
        cv.h.b = __floats2bfloat162_rn(f2, f3);
        *(uint2*)&Wh[(size_t)(i0 + row) * NC + j0 + c4 * 4] = cv.u;
    }
    // transposed block (j0, i0): fp32 + bf16
    if (!diag) {
        #pragma unroll
        for (int it = 0; it < 8; it++) {
            const int e = it * 512 + tid;
            const int n = e >> 5, m4 = e & 31;
            const float f0 = st[(m4 * 4)     * 129 + n], f1 = st[(m4 * 4 + 1) * 129 + n];
            const float f2 = st[(m4 * 4 + 2) * 129 + n], f3 = st[(m4 * 4 + 3) * 129 + n];
            *(float4*)&Wb[(size_t)(j0 + n) * NC + i0 + m4 * 4] = make_float4(f0, f1, f2, f3);
            union { struct { __nv_bfloat162 a, b; } h; uint2 u; } cv;
            cv.h.a = __floats2bfloat162_rn(f0, f1);
            cv.h.b = __floats2bfloat162_rn(f2, f3);
            *(uint2*)&Wh[(size_t)(j0 + n) * NC + i0 + m4 * 4] = cv.u;
        }
    }
}

// =====================================================================
// Kernel 2: 10 power iterations on bf16 Ws. One block/batch, 1024 threads.
// 8-way d-split, each thread 4 consecutive c via uint2 (4 bf16).
// =====================================================================
__global__ __launch_bounds__(1024)
void power_kernel(const float* __restrict__ vin) {
    const int b = blockIdx.x, t = threadIdx.x;
    const int h = t >> 7;        // d-chunk 0..7 (64 d each)
    const int cg = t & 127;      // c-group: c = 4*cg
    __shared__ float vs[NC];
    __shared__ float part[8 * NC];
    __shared__ float red[16];
    __shared__ float tot;

    const __nv_bfloat16* __restrict__ Wh = g_Wsh + (size_t)b * NC * NC;
    if (t < NC) vs[t] = vin[b * NC + t];
    __syncthreads();

    const uint2* __restrict__ base = (const uint2*)(Wh + (size_t)(h * 64) * NC) + cg;

    for (int it = 0; it < NIP; it++) {
        float a0 = 0.f, a1 = 0.f, a2 = 0.f, a3 = 0.f;
        #pragma unroll 16
        for (int d = 0; d < 64; d++) {
            const uint2 p = base[(size_t)d * (NC / 4)];
            const float vv = vs[h * 64 + d];
            a0 += vv * bflo(p.x); a1 += vv * bfhi(p.x);
            a2 += vv * bflo(p.y); a3 += vv * bfhi(p.y);
        }
        *(float4*)&part[h * NC + cg * 4] = make_float4(a0, a1, a2, a3);
        __syncthreads();

        float nv = 0.f;
        if (t < NC) {
            #pragma unroll
            for (int hh = 0; hh < 8; hh++) nv += part[hh * NC + t];
            float s = nv * nv;
            #pragma unroll
            for (int o = 16; o > 0; o >>= 1)
                s += __shfl_xor_sync(0xffffffffu, s, o);
            if ((t & 31) == 0) red[t >> 5] = s;
        }
        __syncthreads();
        if (t == 0) {
            float x = 0.f;
            #pragma unroll
            for (int i = 0; i < 16; i++) x += red[i];
            tot = x;
        }
        __syncthreads();
        if (t < NC) vs[t] = nv * rsqrtf(tot);
        __syncthreads();
    }
    if (t < NC) g_v[b * NC + t] = vs[t];
}

// =====================================================================
// Kernel 3: u partials from bf16 X. grid (2 n-blocks, 8 c-chunks, 16 batches),
// 256 threads, each thread 8 n via uint4 (8 bf16), 64 c.
// =====================================================================
__global__ __launch_bounds__(256)
void u_part_kernel() {
    const int b = blockIdx.z, ch = blockIdx.y;
    const int n0 = blockIdx.x * 2048 + threadIdx.x * 8;
    __shared__ float vsh[64];
    if (threadIdx.x < 64) vsh[threadIdx.x] = g_v[b * NC + ch * 64 + threadIdx.x];
    __syncthreads();

    const __nv_bfloat16* __restrict__ Xp = g_xh + (size_t)b * NC * NHW + (size_t)(ch * 64) * NHW;
    float a[8];
    #pragma unroll
    for (int j = 0; j < 8; j++) a[j] = 0.f;
    #pragma unroll 8
    for (int cc = 0; cc < 64; cc++) {
        const uint4 p = *(const uint4*)&Xp[(size_t)cc * NHW + n0];
        const float vv = vsh[cc];
        a[0] += vv * bflo(p.x); a[1] += vv * bfhi(p.x);
        a[2] += vv * bflo(p.y); a[3] += vv * bfhi(p.y);
        a[4] += vv * bflo(p.z); a[5] += vv * bfhi(p.z);
        a[6] += vv * bflo(p.w); a[7] += vv * bfhi(p.w);
    }
    float* dst = &g_upar[(size_t)(b * 8 + ch) * NHW + n0];
    *(float4*)dst       = make_float4(a[0], a[1], a[2], a[3]);
    *(float4*)(dst + 4) = make_float4(a[4], a[5], a[6], a[7]);
}

// =====================================================================
// Kernel 4: reduce c-chunk partials -> g_u, compute 1/||u||. grid 16, 512 thr.
// =====================================================================
__global__ __launch_bounds__(512)
void u_reduce_kernel() {
    const int b = blockIdx.x, t = threadIdx.x;
    __shared__ float red[16];
    float sq = 0.f;
    #pragma unroll
    for (int j = 0; j < 8; j++) {
        const int n = j * 512 + t;
        float s = 0.f;
        #pragma unroll
        for (int ch = 0; ch < 8; ch++)
            s += g_upar[(size_t)(b * 8 + ch) * NHW + n];
        g_u[b * NHW + n] = s;
        sq += s * s;
    }
    #pragma unroll
    for (int o = 16; o > 0; o >>= 1)
        sq += __shfl_xor_sync(0xffffffffu, sq, o);
    if ((t & 31) == 0) red[t >> 5] = sq;
    __syncthreads();
    if (t == 0) {
        float x = 0.f;
        #pragma unroll
        for (int i = 0; i < 16; i++) x += red[i];
        g_uinv[b] = rsqrtf(x);
    }
}

// =====================================================================
// Kernel 5: out = x + (v * 1/||u||) outer u. float4 streaming (f32 x).
// =====================================================================
__global__ __launch_bounds__(256)
void final_kernel(const float* __restrict__ x, float* __restrict__ out) {
    const size_t i = (size_t)blockIdx.x * 256 + threadIdx.x;   // float4 idx
    const size_t e = i * 4;
    const int b   = (int)(e >> 21);                 // NC*NHW = 2^21
    const int rem = (int)(e & ((1u << 21) - 1));
    const int c   = rem >> 12;                      // NHW = 2^12
    const int n   = rem & (NHW - 1);
    const float vc = g_v[b * NC + c] * g_uinv[b];
    const float4 u4 = *(const float4*)&g_u[b * NHW + n];
    const float4 xv = *(const float4*)&x[e];
    float4 o;
    o.x = xv.x + vc * u4.x;
    o.y = xv.y + vc * u4.y;
    o.z = xv.z + vc * u4.z;
    o.w = xv.w + vc * u4.w;
    *(float4*)&out[e] = o;
}

// =====================================================================
extern "C" void kernel_launch(void* const* d_in, const int* in_sizes, int n_in,
                              void* d_out, int out_size) {
    const float* x  = (const float*)d_in[0];
    const float* v0 = (const float*)d_in[1];
    float* out = (float*)d_out;

    cudaFuncSetAttribute(gram_mma, cudaFuncAttributeMaxDynamicSharedMemorySize, GRAM_SMEM);

    conv_kernel<<<32768, 256>>>(x);                    // 32M elems / (256*4)
    gram_mma<<<dim3(10, NB), 512, GRAM_SMEM>>>();
    power_kernel<<<NB, 1024>>>(v0);
    u_part_kernel<<<dim3(2, 8, NB), 256>>>();
    u_reduce_kernel<<<NB, 512>>>();
    final_kernel<<<32768, 256>>>(x, out);
}